// round 7
// baseline (speedup 1.0000x reference)
#include <cuda_runtime.h>
#include <cuda_bf16.h>
#include <stdint.h>

#define EPSF 1e-6f
#define TPB 256

__device__ double g_acc = 0.0;          // reset by last block every call
__device__ unsigned int g_ticket = 0;   // reset by last block every call

// 4 lanes per sample, 2 samples per lane-group (front-batched loads).
// H = 120 specialization. Single launch; last block finalizes.
__global__ void __launch_bounds__(TPB) runway_loss_h120(
        const float* __restrict__ pred,
        const unsigned char* __restrict__ mask,
        const float* __restrict__ runway,
        float* __restrict__ out,
        int B) {
    const unsigned FULL = 0xFFFFFFFFu;
    int t   = blockIdx.x * TPB + threadIdx.x;
    int G   = t >> 2;           // group id
    int sub = t & 3;            // lane within group
    int s0  = 2 * G;            // first sample
    int s1  = 2 * G + 1;        // second sample
    bool a0 = (s0 < B);
    bool a1 = (s1 < B);

    // ---- front-batched loads: runway dirs + 8 mask uint2-quads ----
    float2 rd0 = make_float2(0.f, 0.f), rd1 = make_float2(0.f, 0.f);
    int ones0 = 0, ones1 = 0;
    {
        int base = sub * 4;                     // uint2 index: 0,4,8,12 (15/row)
        uint2 za = make_uint2(0u, 0u);
        uint2 a0w = za, b0w = za, c0w = za, d0w = za;
        uint2 a1w = za, b1w = za, c1w = za, d1w = za;
        if (a0) {
            const uint2* r0 = (const uint2*)(mask + (size_t)s0 * 120);
            a0w = r0[base]; b0w = r0[base + 1]; c0w = r0[base + 2];
            if (base + 3 < 15) d0w = r0[base + 3];
            rd0 = *(const float2*)(runway + (size_t)s0 * 4 + 2);
        }
        if (a1) {
            const uint2* r1 = (const uint2*)(mask + (size_t)s1 * 120);
            a1w = r1[base]; b1w = r1[base + 1]; c1w = r1[base + 2];
            if (base + 3 < 15) d1w = r1[base + 3];
            rd1 = *(const float2*)(runway + (size_t)s1 * 4 + 2);
        }
        ones0 = __popc(a0w.x) + __popc(a0w.y) + __popc(b0w.x) + __popc(b0w.y)
              + __popc(c0w.x) + __popc(c0w.y) + __popc(d0w.x) + __popc(d0w.y);
        ones1 = __popc(a1w.x) + __popc(a1w.y) + __popc(b1w.x) + __popc(b1w.y)
              + __popc(c1w.x) + __popc(c1w.y) + __popc(d1w.x) + __popc(d1w.y);
    }
    // group reduce both counts (4-lane groups xor-closed under offsets 1,2)
    ones0 += __shfl_xor_sync(FULL, ones0, 1);
    ones0 += __shfl_xor_sync(FULL, ones0, 2);
    ones1 += __shfl_xor_sync(FULL, ones1, 1);
    ones1 += __shfl_xor_sync(FULL, ones1, 2);

    // ---- two independent gathers, issued back-to-back ----
    float px0 = 0.f, py0 = 0.f, px1 = 0.f, py1 = 0.f;
    if (a0) {
        int idx = 120 - ones0 - 4 + sub;
        if (idx < 0) idx = 0;
        if (idx > 119) idx = 119;
        const float* p = pred + (size_t)s0 * 360 + idx * 3;
        px0 = p[0]; py0 = p[1];
    }
    if (a1) {
        int idx = 120 - ones1 - 4 + sub;
        if (idx < 0) idx = 0;
        if (idx > 119) idx = 119;
        const float* p = pred + (size_t)s1 * 360 + idx * 3;
        px1 = p[0]; py1 = p[1];
    }

    // neighbor points within group
    float nx0 = __shfl_down_sync(FULL, px0, 1);
    float ny0 = __shfl_down_sync(FULL, py0, 1);
    float nx1 = __shfl_down_sync(FULL, px1, 1);
    float ny1 = __shfl_down_sync(FULL, py1, 1);

    float term = 0.0f;          // sum of both samples' (1-cos)^2 on this lane
    if (sub < 3) {
        if (a0) {
            float rx = rd0.x, ry = rd0.y;
            float rn = __fsqrt_rn(rx * rx + ry * ry) + EPSF;
            rx = __fdiv_rn(rx, rn);
            ry = __fdiv_rn(ry, rn);
            float dx = nx0 - px0, dy = ny0 - py0;
            float dn = __fsqrt_rn(dx * dx + dy * dy) + EPSF;
            float cs = __fdiv_rn(dx, dn) * rx + __fdiv_rn(dy, dn) * ry;
            float u  = 1.0f - cs;
            term += u * u;
        }
        if (a1) {
            float rx = rd1.x, ry = rd1.y;
            float rn = __fsqrt_rn(rx * rx + ry * ry) + EPSF;
            rx = __fdiv_rn(rx, rn);
            ry = __fdiv_rn(ry, rn);
            float dx = nx1 - px1, dy = ny1 - py1;
            float dn = __fsqrt_rn(dx * dx + dy * dy) + EPSF;
            float cs = __fdiv_rn(dx, dn) * rx + __fdiv_rn(dy, dn) * ry;
            float u  = 1.0f - cs;
            term += u * u;
        }
    }
    // group reduce, then scale by 1/3 (mean over the 3 directions)
    term += __shfl_xor_sync(FULL, term, 1);
    term += __shfl_xor_sync(FULL, term, 2);
    float per = (sub == 0) ? __fdiv_rn(term, 3.0f) : 0.0f;

    // ---- warp reduce ----
    per += __shfl_xor_sync(FULL, per, 4);
    per += __shfl_xor_sync(FULL, per, 8);
    per += __shfl_xor_sync(FULL, per, 16);

    // ---- block reduce: one double atomic per block, then last-block finalize ----
    __shared__ float wsum[TPB / 32];
    int lane = threadIdx.x & 31;
    int wid  = threadIdx.x >> 5;
    if (lane == 0) wsum[wid] = per;
    __syncthreads();
    if (threadIdx.x == 0) {
        float bsum = 0.0f;
        #pragma unroll
        for (int i = 0; i < TPB / 32; i++) bsum += wsum[i];
        atomicAdd(&g_acc, (double)bsum);
        __threadfence();
        unsigned int tkt = atomicAdd(&g_ticket, 1u);
        if (tkt == gridDim.x - 1) {
            out[0] = (float)(g_acc / (double)B);
            g_acc = 0.0;
            g_ticket = 0;
        }
    }
}

// Generic fallback (thread-per-sample) for unexpected H. Same single-launch pattern.
__global__ void __launch_bounds__(TPB) runway_loss_generic(
        const float* __restrict__ pred,
        const unsigned char* __restrict__ mask,
        const float* __restrict__ runway,
        float* __restrict__ out,
        int B, int H) {
    int s = blockIdx.x * blockDim.x + threadIdx.x;
    float contrib = 0.0f;
    if (s < B) {
        const unsigned char* mrow = mask + (size_t)s * H;
        int ones = 0;
        for (int i = 0; i < H; i++) ones += (int)mrow[i];
        int L = H - ones;
        float rx = runway[(size_t)s * 4 + 2];
        float ry = runway[(size_t)s * 4 + 3];
        float rn = __fsqrt_rn(rx * rx + ry * ry) + EPSF;
        rx = __fdiv_rn(rx, rn);
        ry = __fdiv_rn(ry, rn);
        const float* prow = pred + (size_t)s * H * 3;
        float px[4], py[4];
        for (int j = 0; j < 4; j++) {
            int idx = L - 4 + j;
            if (idx < 0) idx = 0;
            if (idx > H - 1) idx = H - 1;
            px[j] = prow[idx * 3 + 0];
            py[j] = prow[idx * 3 + 1];
        }
        float acc = 0.0f;
        for (int j = 0; j < 3; j++) {
            float dx = px[j + 1] - px[j];
            float dy = py[j + 1] - py[j];
            float dn = __fsqrt_rn(dx * dx + dy * dy) + EPSF;
            float cs = __fdiv_rn(dx, dn) * rx + __fdiv_rn(dy, dn) * ry;
            float u  = 1.0f - cs;
            acc += u * u;
        }
        contrib = __fdiv_rn(acc, 3.0f);
    }
    __shared__ float red[TPB];
    red[threadIdx.x] = contrib;
    __syncthreads();
    for (int o = TPB / 2; o >= 32; o >>= 1) {
        if (threadIdx.x < o) red[threadIdx.x] += red[threadIdx.x + o];
        __syncthreads();
    }
    if (threadIdx.x < 32) {
        float v = red[threadIdx.x];
        for (int o = 16; o; o >>= 1)
            v += __shfl_xor_sync(0xFFFFFFFFu, v, o);
        if (threadIdx.x == 0) {
            atomicAdd(&g_acc, (double)v);
            __threadfence();
            unsigned int tkt = atomicAdd(&g_ticket, 1u);
            if (tkt == gridDim.x - 1) {
                out[0] = (float)(g_acc / (double)B);
                g_acc = 0.0;
                g_ticket = 0;
            }
        }
    }
}

extern "C" void kernel_launch(void* const* d_in, const int* in_sizes, int n_in,
                              void* d_out, int out_size) {
    const float*         pred   = (const float*)d_in[0];
    // d_in[1] = target_abs (unused by the reference)
    const unsigned char* mask   = (const unsigned char*)d_in[2];
    const float*         runway = (const float*)d_in[3];
    float*               out    = (float*)d_out;

    int B = in_sizes[3] / 4;          // runway is (B, 4)
    int H = in_sizes[2] / B;          // mask is (B, H)

    if (H == 120) {
        int groups  = (B + 1) / 2;            // 2 samples per 4-lane group
        int threads = groups * 4;
        int blocks  = (threads + TPB - 1) / TPB;
        runway_loss_h120<<<blocks, TPB>>>(pred, mask, runway, out, B);
    } else {
        int blocks = (B + TPB - 1) / TPB;
        runway_loss_generic<<<blocks, TPB>>>(pred, mask, runway, out, B, H);
    }
}

// round 8
// speedup vs baseline: 1.0269x; 1.0269x over previous
#include <cuda_runtime.h>
#include <cuda_bf16.h>
#include <stdint.h>

#define EPSF 1e-6f
#define TPB 256

__device__ double g_acc = 0.0;          // reset by last block every call
__device__ unsigned int g_ticket = 0;   // reset by last block every call

// 8 lanes cooperate per sample. H = 120 specialization.
// Single launch; last block finalizes.
__global__ void __launch_bounds__(TPB) runway_loss_h120(
        const float* __restrict__ pred,
        const unsigned char* __restrict__ mask,
        const float* __restrict__ runway,
        float* __restrict__ out,
        int B) {
    const unsigned FULL = 0xFFFFFFFFu;
    int t   = blockIdx.x * TPB + threadIdx.x;
    int g   = t >> 3;          // sample index
    int sub = t & 7;           // lane within 8-lane group
    bool active = (g < B);

    // ---- mask popcount: each lane reads up to 2 uint2 (15 uint2 per 120B row) ----
    int ones = 0;
    if (active) {
        const uint2* row = (const uint2*)(mask + (size_t)g * 120);
        int base = sub * 2;                    // 0,2,...,14
        uint2 a = row[base];
        uint2 b = make_uint2(0u, 0u);
        if (base + 1 < 15) b = row[base + 1];  // lane 7 reads only one
        ones = __popc(a.x) + __popc(a.y) + __popc(b.x) + __popc(b.y);
    }
    // group reduce (8-lane groups xor-closed under offsets 1,2,4)
    ones += __shfl_xor_sync(FULL, ones, 1);
    ones += __shfl_xor_sync(FULL, ones, 2);
    ones += __shfl_xor_sync(FULL, ones, 4);

    // ---- lanes 0..3 gather the 4 trailing points; load runway dir ----
    float px = 0.0f, py = 0.0f;
    float2 rdir = make_float2(0.0f, 0.0f);
    if (active && sub < 4) {
        int idx = 120 - ones - 4 + sub;        // L - 4 + sub
        if (idx < 0) idx = 0;
        if (idx > 119) idx = 119;
        const float* p = pred + (size_t)g * 360 + idx * 3;
        px = p[0];
        py = p[1];
        rdir = *(const float2*)(runway + (size_t)g * 4 + 2);
    }

    // neighbor point (lane sub gets lane sub+1's point; valid for sub<3)
    float nx = __shfl_down_sync(FULL, px, 1);
    float ny = __shfl_down_sync(FULL, py, 1);

    float term = 0.0f;
    if (active && sub < 3) {
        float rx = rdir.x, ry = rdir.y;
        float rn = __fsqrt_rn(rx * rx + ry * ry) + EPSF;
        rx = __fdiv_rn(rx, rn);
        ry = __fdiv_rn(ry, rn);

        float dx = nx - px;
        float dy = ny - py;
        float dn = __fsqrt_rn(dx * dx + dy * dy) + EPSF;
        float cs = __fdiv_rn(dx, dn) * rx + __fdiv_rn(dy, dn) * ry;
        float u  = 1.0f - cs;
        term = u * u;
    }
    // sum the 3 terms onto lane sub==0 of the group (lanes 3..7 hold 0)
    term += __shfl_xor_sync(FULL, term, 1);
    term += __shfl_xor_sync(FULL, term, 2);
    float per = (sub == 0) ? __fdiv_rn(term, 3.0f) : 0.0f;

    // ---- warp reduce (only sub==0 lanes nonzero) ----
    per += __shfl_xor_sync(FULL, per, 8);
    per += __shfl_xor_sync(FULL, per, 16);

    // ---- block reduce: one double atomic per block, then last-block finalize ----
    __shared__ float wsum[TPB / 32];
    int lane = threadIdx.x & 31;
    int wid  = threadIdx.x >> 5;
    if (lane == 0) wsum[wid] = per;
    __syncthreads();
    if (threadIdx.x == 0) {
        float bsum = 0.0f;
        #pragma unroll
        for (int i = 0; i < TPB / 32; i++) bsum += wsum[i];
        atomicAdd(&g_acc, (double)bsum);
        __threadfence();
        unsigned int tkt = atomicAdd(&g_ticket, 1u);
        if (tkt == gridDim.x - 1) {
            out[0] = (float)(g_acc / (double)B);
            g_acc = 0.0;
            g_ticket = 0;
        }
    }
}

// Generic fallback (thread-per-sample) for unexpected H. Same single-launch pattern.
__global__ void __launch_bounds__(TPB) runway_loss_generic(
        const float* __restrict__ pred,
        const unsigned char* __restrict__ mask,
        const float* __restrict__ runway,
        float* __restrict__ out,
        int B, int H) {
    int s = blockIdx.x * blockDim.x + threadIdx.x;
    float contrib = 0.0f;
    if (s < B) {
        const unsigned char* mrow = mask + (size_t)s * H;
        int ones = 0;
        for (int i = 0; i < H; i++) ones += (int)mrow[i];
        int L = H - ones;
        float rx = runway[(size_t)s * 4 + 2];
        float ry = runway[(size_t)s * 4 + 3];
        float rn = __fsqrt_rn(rx * rx + ry * ry) + EPSF;
        rx = __fdiv_rn(rx, rn);
        ry = __fdiv_rn(ry, rn);
        const float* prow = pred + (size_t)s * H * 3;
        float px[4], py[4];
        for (int j = 0; j < 4; j++) {
            int idx = L - 4 + j;
            if (idx < 0) idx = 0;
            if (idx > H - 1) idx = H - 1;
            px[j] = prow[idx * 3 + 0];
            py[j] = prow[idx * 3 + 1];
        }
        float acc = 0.0f;
        for (int j = 0; j < 3; j++) {
            float dx = px[j + 1] - px[j];
            float dy = py[j + 1] - py[j];
            float dn = __fsqrt_rn(dx * dx + dy * dy) + EPSF;
            float cs = __fdiv_rn(dx, dn) * rx + __fdiv_rn(dy, dn) * ry;
            float u  = 1.0f - cs;
            acc += u * u;
        }
        contrib = __fdiv_rn(acc, 3.0f);
    }
    __shared__ float red[TPB];
    red[threadIdx.x] = contrib;
    __syncthreads();
    for (int o = TPB / 2; o >= 32; o >>= 1) {
        if (threadIdx.x < o) red[threadIdx.x] += red[threadIdx.x + o];
        __syncthreads();
    }
    if (threadIdx.x < 32) {
        float v = red[threadIdx.x];
        for (int o = 16; o; o >>= 1)
            v += __shfl_xor_sync(0xFFFFFFFFu, v, o);
        if (threadIdx.x == 0) {
            atomicAdd(&g_acc, (double)v);
            __threadfence();
            unsigned int tkt = atomicAdd(&g_ticket, 1u);
            if (tkt == gridDim.x - 1) {
                out[0] = (float)(g_acc / (double)B);
                g_acc = 0.0;
                g_ticket = 0;
            }
        }
    }
}

extern "C" void kernel_launch(void* const* d_in, const int* in_sizes, int n_in,
                              void* d_out, int out_size) {
    const float*         pred   = (const float*)d_in[0];
    // d_in[1] = target_abs (unused by the reference)
    const unsigned char* mask   = (const unsigned char*)d_in[2];
    const float*         runway = (const float*)d_in[3];
    float*               out    = (float*)d_out;

    int B = in_sizes[3] / 4;          // runway is (B, 4)
    int H = in_sizes[2] / B;          // mask is (B, H)

    if (H == 120) {
        long long threads = (long long)B * 8;
        int blocks = (int)((threads + TPB - 1) / TPB);
        runway_loss_h120<<<blocks, TPB>>>(pred, mask, runway, out, B);
    } else {
        int blocks = (B + TPB - 1) / TPB;
        runway_loss_generic<<<blocks, TPB>>>(pred, mask, runway, out, B, H);
    }
}